// round 1
// baseline (speedup 1.0000x reference)
#include <cuda_runtime.h>
#include <cuda_bf16.h>
#include <math.h>

// Problem constants
#define BATCH 32
#define NROI  400
#define CDIM  720
#define HEADS 12
#define HD    60          // head dim
#define M_TOT (BATCH*NROI)        // 12800
#define QK_COLS (2*CDIM)          // 1440 (q and k weight rows only; v unused)
#define BH    (BATCH*HEADS)       // 384

// Scratch (allocation-free rule: __device__ globals)
__device__ float g_q[BATCH*HEADS*NROI*HD];   // (b,h,n,e) 36.9 MB
__device__ float g_k[BATCH*HEADS*NROI*HD];   // (b,h,n,e) 36.9 MB
__device__ int   g_roim[M_TOT];              // roi valid flag per (b,n)

// ---------------------------------------------------------------------------
// Kernel 1: roi_mask[b,n] = any(mask[b,:,n] != 0)
// ---------------------------------------------------------------------------
__global__ void roi_mask_kernel(const int* __restrict__ mask) {
    int idx = blockIdx.x * blockDim.x + threadIdx.x;   // b*400+n
    if (idx >= M_TOT) return;
    int b = idx / NROI, n = idx % NROI;
    const int* p = mask + (size_t)b * CDIM * NROI + n;
    int s = 0;
    for (int c = 0; c < CDIM; c++) {
        s |= p[(size_t)c * NROI];
        if (s) break;
    }
    g_roim[idx] = (s != 0);
}

// ---------------------------------------------------------------------------
// Kernel 2: QK projection GEMM.
//   out[m, d] = sum_c x[m,c] * w[d,c],  m in [0,12800), d in [0,1440)
//   d <  720 : q, h = d/60, e = d%60
//   d >= 720 : k, likewise with d-720
// Tiling: BM=BN=64, BK=16, 256 threads, 4x4 per thread.
// ---------------------------------------------------------------------------
#define BM 64
#define BN 64
#define BK 16

__global__ __launch_bounds__(256) void gemm_qk_kernel(const float* __restrict__ x,
                                                      const float* __restrict__ w) {
    __shared__ float As[BK][BM + 4];
    __shared__ float Bs[BK][BN + 4];

    const int m0 = blockIdx.y * BM;
    const int d0 = blockIdx.x * BN;
    const int tid = threadIdx.x;
    const int tx = tid & 15;          // 0..15 (N direction)
    const int ty = tid >> 4;          // 0..15 (M direction)
    const int lr = tid >> 2;          // loader row 0..63
    const int lc = (tid & 3) * 4;     // loader col 0,4,8,12

    float acc[4][4];
#pragma unroll
    for (int i = 0; i < 4; i++)
#pragma unroll
        for (int j = 0; j < 4; j++) acc[i][j] = 0.f;

    for (int k0 = 0; k0 < CDIM; k0 += BK) {
        // A tile: x[(m0+lr), k0+lc..+3]  (always in-bounds: 12800 % 64 == 0)
        float4 av = *(const float4*)(x + (size_t)(m0 + lr) * CDIM + k0 + lc);
        As[lc + 0][lr] = av.x;
        As[lc + 1][lr] = av.y;
        As[lc + 2][lr] = av.z;
        As[lc + 3][lr] = av.w;
        // B tile: w[(d0+lr), k0+lc..+3]  (d0+lr <= 1471 < 2160: in-bounds)
        float4 bv = *(const float4*)(w + (size_t)(d0 + lr) * CDIM + k0 + lc);
        Bs[lc + 0][lr] = bv.x;
        Bs[lc + 1][lr] = bv.y;
        Bs[lc + 2][lr] = bv.z;
        Bs[lc + 3][lr] = bv.w;
        __syncthreads();

#pragma unroll
        for (int kk = 0; kk < BK; kk++) {
            float a[4], b[4];
#pragma unroll
            for (int i = 0; i < 4; i++) a[i] = As[kk][ty * 4 + i];
#pragma unroll
            for (int j = 0; j < 4; j++) b[j] = Bs[kk][tx * 4 + j];
#pragma unroll
            for (int i = 0; i < 4; i++)
#pragma unroll
                for (int j = 0; j < 4; j++) acc[i][j] += a[i] * b[j];
        }
        __syncthreads();
    }

    // Epilogue: scatter into (b,h,n,e) layouts for q / k.
#pragma unroll
    for (int i = 0; i < 4; i++) {
        int m = m0 + ty * 4 + i;
        int bb = m / NROI;
        int n  = m % NROI;
#pragma unroll
        for (int j = 0; j < 4; j++) {
            int d = d0 + tx * 4 + j;
            if (d >= QK_COLS) continue;
            float v = acc[i][j];
            if (d < CDIM) {
                int h = d / HD, e = d % HD;
                g_q[(((size_t)bb * HEADS + h) * NROI + n) * HD + e] = v;
            } else {
                int dd = d - CDIM;
                int h = dd / HD, e = dd % HD;
                g_k[(((size_t)bb * HEADS + h) * NROI + n) * HD + e] = v;
            }
        }
    }
}

// ---------------------------------------------------------------------------
// Kernel 3: batched logits GEMM + scale + roi mask, written into d_out.
//   out[bh, n, m] = scale * dot(q[bh,n,:], k[bh,m,:])   (or -10000 if roi off)
// One (64x64) tile per block, full K=60 in one smem pass. grid (7,7,384).
// ---------------------------------------------------------------------------
__global__ __launch_bounds__(256) void logits_kernel(float* __restrict__ out) {
    __shared__ float Qs[HD][BM + 4];
    __shared__ float Ks[HD][BN + 4];

    const int bh = blockIdx.z;            // b*12 + h
    const int b  = bh / HEADS;
    const int n0 = blockIdx.y * BM;       // query rows
    const int c0 = blockIdx.x * BN;       // key cols
    const int tid = threadIdx.x;
    const int tx = tid & 15;
    const int ty = tid >> 4;

    const size_t bh_off = (size_t)bh * NROI * HD;
    const float scale = rsqrtf((float)HD);

    // cooperative load of 64x60 q tile and 64x60 k tile
    for (int i = tid; i < BM * HD; i += 256) {
        int r = i / HD, c = i % HD;
        int qrow = n0 + r;
        Qs[c][r] = (qrow < NROI) ? g_q[bh_off + (size_t)qrow * HD + c] : 0.f;
        int krow = c0 + r;
        Ks[c][r] = (krow < NROI) ? g_k[bh_off + (size_t)krow * HD + c] : 0.f;
    }
    __syncthreads();

    float acc[4][4];
#pragma unroll
    for (int i = 0; i < 4; i++)
#pragma unroll
        for (int j = 0; j < 4; j++) acc[i][j] = 0.f;

#pragma unroll 4
    for (int kk = 0; kk < HD; kk++) {
        float a[4], bb_[4];
#pragma unroll
        for (int i = 0; i < 4; i++) a[i] = Qs[kk][ty * 4 + i];
#pragma unroll
        for (int j = 0; j < 4; j++) bb_[j] = Ks[kk][tx * 4 + j];
#pragma unroll
        for (int i = 0; i < 4; i++)
#pragma unroll
            for (int j = 0; j < 4; j++) acc[i][j] += a[i] * bb_[j];
    }

    // epilogue: scale + roi mask, write to out (B,H,N,N)
#pragma unroll
    for (int i = 0; i < 4; i++) {
        int n = n0 + ty * 4 + i;
        if (n >= NROI) continue;
        float* row = out + ((size_t)bh * NROI + n) * NROI;
#pragma unroll
        for (int j = 0; j < 4; j++) {
            int m = c0 + tx * 4 + j;
            if (m >= NROI) continue;
            float v = acc[i][j] * scale;
            if (!g_roim[b * NROI + m]) v = -10000.0f;
            row[m] = v;
        }
    }
}

// ---------------------------------------------------------------------------
// Kernel 4: in-place row softmax on d_out. One warp per row of 400.
// ---------------------------------------------------------------------------
__global__ __launch_bounds__(256) void softmax_kernel(float* __restrict__ out) {
    const int row = blockIdx.x * 8 + (threadIdx.x >> 5);
    if (row >= BH * NROI) return;
    const int lane = threadIdx.x & 31;
    float* p = out + (size_t)row * NROI;

    float v[13];
    float mx = -1e30f;
#pragma unroll
    for (int t = 0; t < 13; t++) {
        int c = lane + t * 32;
        v[t] = (c < NROI) ? p[c] : -1e30f;
        mx = fmaxf(mx, v[t]);
    }
#pragma unroll
    for (int o = 16; o; o >>= 1) mx = fmaxf(mx, __shfl_xor_sync(0xffffffffu, mx, o));

    float s = 0.f;
#pragma unroll
    for (int t = 0; t < 13; t++) {
        v[t] = __expf(v[t] - mx);   // padded lanes: exp(-1e30) == 0
        s += v[t];
    }
#pragma unroll
    for (int o = 16; o; o >>= 1) s += __shfl_xor_sync(0xffffffffu, s, o);
    float inv = 1.f / s;

#pragma unroll
    for (int t = 0; t < 13; t++) {
        int c = lane + t * 32;
        if (c < NROI) p[c] = v[t] * inv;
    }
}

// ---------------------------------------------------------------------------
extern "C" void kernel_launch(void* const* d_in, const int* in_sizes, int n_in,
                              void* d_out, int out_size) {
    const float* x    = (const float*)d_in[0];   // (32,400,720) f32
    const int*   mask = (const int*)  d_in[1];   // (32,720,400) i32
    const float* w    = (const float*)d_in[2];   // (2160,720)  f32
    float* out = (float*)d_out;                  // (32,12,400,400) f32

    roi_mask_kernel<<<(M_TOT + 255) / 256, 256>>>(mask);

    dim3 g2((QK_COLS + BN - 1) / BN, M_TOT / BM);   // (23, 200)
    gemm_qk_kernel<<<g2, 256>>>(x, w);

    dim3 g3((NROI + BN - 1) / BN, (NROI + BM - 1) / BM, BH);  // (7,7,384)
    logits_kernel<<<g3, 256>>>(out);

    softmax_kernel<<<(BH * NROI + 7) / 8, 256>>>(out);
}

// round 4
// speedup vs baseline: 1.3814x; 1.3814x over previous
#include <cuda_runtime.h>
#include <cuda_bf16.h>
#include <math.h>
#include <stdint.h>

// ---------------------------------------------------------------------------
// Problem constants
// ---------------------------------------------------------------------------
#define BATCH 32
#define NROI  400
#define CDIM  720
#define HEADS 12
#define HD    60
#define M_TOT (BATCH*NROI)        // 12800
#define DTOT  1440                // q+k cols (v unused)
#define DPAD  1536                // grid padding (w has 2160 rows: safe to read)
#define BH    (BATCH*HEADS)       // 384

// GEMM1 tiling
#define BM1 128
#define BN1 128
#define BK1 48
#define NK_ITER (CDIM/BK1)        // 15
#define PITCH_B 112               // bytes per smem row (96 data + 16 pad)
#define TILE_BYTES (BM1*PITCH_B)  // 14336
#define STAGE_BYTES (4*TILE_BYTES)         // A_hi A_lo B_hi B_lo = 57344
#define SMEM1_DYN (2*STAGE_BYTES)          // 114688

// ---------------------------------------------------------------------------
// Device scratch (allocation-free rule)
// ---------------------------------------------------------------------------
__device__ __align__(256) float g_q[(size_t)BH*NROI*HD];
__device__ __align__(256) float g_k[(size_t)BH*NROI*HD];
__device__ int g_roim[M_TOT];
__device__ __align__(256) __nv_bfloat16 g_xhi[(size_t)M_TOT*CDIM];
__device__ __align__(256) __nv_bfloat16 g_xlo[(size_t)M_TOT*CDIM];
__device__ __align__(256) __nv_bfloat16 g_whi[(size_t)DPAD*CDIM];
__device__ __align__(256) __nv_bfloat16 g_wlo[(size_t)DPAD*CDIM];

// ---------------------------------------------------------------------------
// PTX helpers — compute_103-safe only (mma.sync / ldmatrix / cp.async)
// ---------------------------------------------------------------------------
__device__ __forceinline__ uint32_t smem_u32(const void* p) {
    uint32_t a;
    asm("{ .reg .u64 t; cvta.to.shared.u64 t, %1; cvt.u32.u64 %0, t; }" : "=r"(a) : "l"(p));
    return a;
}
__device__ __forceinline__ void cp_async16(uint32_t saddr, const void* gaddr) {
    asm volatile("cp.async.cg.shared.global [%0], [%1], 16;" :: "r"(saddr), "l"(gaddr));
}
#define CP_COMMIT() asm volatile("cp.async.commit_group;")
#define CP_WAIT(n)  asm volatile("cp.async.wait_group %0;" :: "n"(n))

__device__ __forceinline__ void ldm_x4(uint32_t* r, uint32_t addr) {
    asm volatile("ldmatrix.sync.aligned.m8n8.x4.shared.b16 {%0,%1,%2,%3}, [%4];"
                 : "=r"(r[0]), "=r"(r[1]), "=r"(r[2]), "=r"(r[3]) : "r"(addr));
}
__device__ __forceinline__ void ldm_x2(uint32_t* r, uint32_t addr) {
    asm volatile("ldmatrix.sync.aligned.m8n8.x2.shared.b16 {%0,%1}, [%2];"
                 : "=r"(r[0]), "=r"(r[1]) : "r"(addr));
}
__device__ __forceinline__ void mma_bf16(float* d, const uint32_t* a, const uint32_t* b) {
    asm volatile(
        "mma.sync.aligned.m16n8k16.row.col.f32.bf16.bf16.f32 "
        "{%0,%1,%2,%3}, {%4,%5,%6,%7}, {%8,%9}, {%0,%1,%2,%3};"
        : "+f"(d[0]), "+f"(d[1]), "+f"(d[2]), "+f"(d[3])
        : "r"(a[0]), "r"(a[1]), "r"(a[2]), "r"(a[3]), "r"(b[0]), "r"(b[1]));
}

// ---------------------------------------------------------------------------
// Kernel 0: fp32 -> bf16 hi/lo split (x rows, then w rows 0..DPAD-1)
// ---------------------------------------------------------------------------
__global__ void convert_kernel(const float* __restrict__ x, const float* __restrict__ w) {
    int idx = blockIdx.x * 256 + threadIdx.x;
    const int pairs = CDIM / 2;                     // 360
    const int total = (M_TOT + DPAD) * pairs;
    if (idx >= total) return;
    int row = idx / pairs;
    int c = (idx - row * pairs) * 2;
    const float* src;
    __nv_bfloat16 *hi, *lo;
    if (row < M_TOT) {
        src = x + (size_t)row * CDIM;
        hi = g_xhi + (size_t)row * CDIM; lo = g_xlo + (size_t)row * CDIM;
    } else {
        int r = row - M_TOT;
        src = w + (size_t)r * CDIM;
        hi = g_whi + (size_t)r * CDIM; lo = g_wlo + (size_t)r * CDIM;
    }
    float a0 = src[c], a1 = src[c + 1];
    __nv_bfloat16 h0 = __float2bfloat16(a0), h1 = __float2bfloat16(a1);
    hi[c] = h0; hi[c + 1] = h1;
    lo[c]     = __float2bfloat16(a0 - __bfloat162float(h0));
    lo[c + 1] = __float2bfloat16(a1 - __bfloat162float(h1));
}

// ---------------------------------------------------------------------------
// Kernel 1: roi_mask[b,n] = any(mask[b,:,n] != 0)
// ---------------------------------------------------------------------------
__global__ void roi_mask_kernel(const int* __restrict__ mask) {
    int idx = blockIdx.x * blockDim.x + threadIdx.x;
    if (idx >= M_TOT) return;
    int b = idx / NROI, n = idx % NROI;
    const int* p = mask + (size_t)b * CDIM * NROI + n;
    int s = 0;
    for (int c = 0; c < CDIM; c++) {
        s |= p[(size_t)c * NROI];
        if (s) break;
    }
    g_roim[idx] = (s != 0);
}

// ---------------------------------------------------------------------------
// Kernel 2: HMMA bf16-split GEMM.  D[m,d] = sum_c x[m,c]*w[d,c]
// grid (DPAD/128=12, M_TOT/128=100), 256 threads (8 warps, 2x4).
// ---------------------------------------------------------------------------
__device__ __forceinline__ void issue_stage_loads(uint32_t sbase,
                                                  int m0, int d0, int k0, int tid) {
    // 4 tiles x 768 16B-chunks, 6 chunks (96B) per 128 rows
    const __nv_bfloat16* gsrc[4] = {g_xhi, g_xlo, g_whi, g_wlo};
    const int row0[4] = {m0, m0, d0, d0};
#pragma unroll
    for (int t = 0; t < 4; t++) {
        uint32_t sb = sbase + t * TILE_BYTES;
        const __nv_bfloat16* g = gsrc[t];
#pragma unroll
        for (int it = 0; it < 3; it++) {
            int c = tid + it * 256;               // 0..767
            int r = c / 6, ch = c - r * 6;
            cp_async16(sb + r * PITCH_B + ch * 16,
                       g + (size_t)(row0[t] + r) * CDIM + k0 + ch * 8);
        }
    }
}

__global__ __launch_bounds__(256, 1) void gemm_qk_mma_kernel() {
    extern __shared__ __align__(128) char sm[];

    const int tid = threadIdx.x;
    const int wid = tid >> 5;
    const int lane = tid & 31;
    const int warp_m = wid >> 2;          // 0..1 : 64 rows each
    const int warp_n = wid & 3;           // 0..3 : 32 cols each
    const int m0 = blockIdx.y * BM1;
    const int d0 = blockIdx.x * BN1;

    const uint32_t sbase = smem_u32(sm);

    float acc[4][4][4];
#pragma unroll
    for (int i = 0; i < 4; i++)
#pragma unroll
        for (int j = 0; j < 4; j++)
#pragma unroll
            for (int e = 0; e < 4; e++) acc[i][j][e] = 0.f;

    issue_stage_loads(sbase, m0, d0, 0, tid);
    CP_COMMIT();

    // per-lane ldmatrix base offsets
    const int a_row = warp_m * 64 + (lane & 15);
    const int a_colb = (lane >> 4) * 16;                 // byte offset of k-half
    const int b_row = warp_n * 32 + (lane & 7);
    const int b_colb = ((lane >> 3) & 1) * 16;

    for (int kt = 0; kt < NK_ITER; kt++) {
        if (kt + 1 < NK_ITER) {
            issue_stage_loads(sbase + ((kt + 1) & 1) * STAGE_BYTES, m0, d0,
                              (kt + 1) * BK1, tid);
            CP_COMMIT();
            CP_WAIT(1);
        } else {
            CP_WAIT(0);
        }
        __syncthreads();

        uint32_t st = sbase + (kt & 1) * STAGE_BYTES;
        uint32_t a_hi_s = st;
        uint32_t a_lo_s = st + TILE_BYTES;
        uint32_t b_hi_s = st + 2 * TILE_BYTES;
        uint32_t b_lo_s = st + 3 * TILE_BYTES;

#pragma unroll
        for (int ks = 0; ks < BK1 / 16; ks++) {          // 3 k16 steps
            uint32_t ahi[4][4], alo[4][4];
#pragma unroll
            for (int mf = 0; mf < 4; mf++) {
                uint32_t off = (uint32_t)(a_row + mf * 16) * PITCH_B + ks * 32 + a_colb;
                ldm_x4(ahi[mf], a_hi_s + off);
                ldm_x4(alo[mf], a_lo_s + off);
            }
            uint32_t bhi[4][2], blo[4][2];
#pragma unroll
            for (int nf = 0; nf < 4; nf++) {
                uint32_t off = (uint32_t)(b_row + nf * 8) * PITCH_B + ks * 32 + b_colb;
                ldm_x2(bhi[nf], b_hi_s + off);
                ldm_x2(blo[nf], b_lo_s + off);
            }
#pragma unroll
            for (int mf = 0; mf < 4; mf++)
#pragma unroll
                for (int nf = 0; nf < 4; nf++) {
                    mma_bf16(acc[mf][nf], ahi[mf], bhi[nf]);
                    mma_bf16(acc[mf][nf], ahi[mf], blo[nf]);
                    mma_bf16(acc[mf][nf], alo[mf], bhi[nf]);
                }
        }
        __syncthreads();
    }

    // Epilogue: regs -> smem (fp32, pitch 132) -> coalesced scatter
    float* stage = (float*)sm;            // 128 x 132 floats = 67.6KB <= SMEM1_DYN
#pragma unroll
    for (int mf = 0; mf < 4; mf++)
#pragma unroll
        for (int nf = 0; nf < 4; nf++) {
            int r0 = warp_m * 64 + mf * 16 + (lane >> 2);
            int c0 = warp_n * 32 + nf * 8 + (lane & 3) * 2;
            stage[r0 * 132 + c0]           = acc[mf][nf][0];
            stage[r0 * 132 + c0 + 1]       = acc[mf][nf][1];
            stage[(r0 + 8) * 132 + c0]     = acc[mf][nf][2];
            stage[(r0 + 8) * 132 + c0 + 1] = acc[mf][nf][3];
        }
    __syncthreads();

    // FIXED: q/k routing decided PER COLUMN (720 is not 128-aligned).
    for (int i = tid; i < BM1 * BN1; i += 256) {
        int r = i >> 7, col = i & 127;
        int d = d0 + col;
        if (d >= DTOT) continue;
        int m = m0 + r;
        int b = m / NROI, n = m - b * NROI;
        float v = stage[r * 132 + col];
        if (d < CDIM) {
            int h = d / HD, e = d - h * HD;
            g_q[(((size_t)b * HEADS + h) * NROI + n) * HD + e] = v;
        } else {
            int dd = d - CDIM;
            int h = dd / HD, e = dd - h * HD;
            g_k[(((size_t)b * HEADS + h) * NROI + n) * HD + e] = v;
        }
    }
}

// ---------------------------------------------------------------------------
// Kernel 3: batched logits GEMM + scale + roi mask (fp32)
// ---------------------------------------------------------------------------
#define BM 64
#define BN 64
__global__ __launch_bounds__(256) void logits_kernel(float* __restrict__ out) {
    __shared__ float Qs[HD][BM + 4];
    __shared__ float Ks[HD][BN + 4];

    const int bh = blockIdx.z;
    const int b  = bh / HEADS;
    const int n0 = blockIdx.y * BM;
    const int c0 = blockIdx.x * BN;
    const int tid = threadIdx.x;
    const int tx = tid & 15;
    const int ty = tid >> 4;

    const size_t bh_off = (size_t)bh * NROI * HD;
    const float scale = rsqrtf((float)HD);

    for (int i = tid; i < BM * HD; i += 256) {
        int r = i / HD, c = i % HD;
        int qrow = n0 + r;
        Qs[c][r] = (qrow < NROI) ? g_q[bh_off + (size_t)qrow * HD + c] : 0.f;
        int krow = c0 + r;
        Ks[c][r] = (krow < NROI) ? g_k[bh_off + (size_t)krow * HD + c] : 0.f;
    }
    __syncthreads();

    float acc[4][4];
#pragma unroll
    for (int i = 0; i < 4; i++)
#pragma unroll
        for (int j = 0; j < 4; j++) acc[i][j] = 0.f;

#pragma unroll 4
    for (int kk = 0; kk < HD; kk++) {
        float a[4], bb_[4];
#pragma unroll
        for (int i = 0; i < 4; i++) a[i] = Qs[kk][ty * 4 + i];
#pragma unroll
        for (int j = 0; j < 4; j++) bb_[j] = Ks[kk][tx * 4 + j];
#pragma unroll
        for (int i = 0; i < 4; i++)
#pragma unroll
            for (int j = 0; j < 4; j++) acc[i][j] += a[i] * bb_[j];
    }

#pragma unroll
    for (int i = 0; i < 4; i++) {
        int n = n0 + ty * 4 + i;
        if (n >= NROI) continue;
        float* row = out + ((size_t)bh * NROI + n) * NROI;
#pragma unroll
        for (int j = 0; j < 4; j++) {
            int m = c0 + tx * 4 + j;
            if (m >= NROI) continue;
            float v = acc[i][j] * scale;
            if (!g_roim[b * NROI + m]) v = -10000.0f;
            row[m] = v;
        }
    }
}

// ---------------------------------------------------------------------------
// Kernel 4: in-place row softmax. One warp per row of 400.
// ---------------------------------------------------------------------------
__global__ __launch_bounds__(256) void softmax_kernel(float* __restrict__ out) {
    const int row = blockIdx.x * 8 + (threadIdx.x >> 5);
    if (row >= BH * NROI) return;
    const int lane = threadIdx.x & 31;
    float* p = out + (size_t)row * NROI;

    float v[13];
    float mx = -1e30f;
#pragma unroll
    for (int t = 0; t < 13; t++) {
        int c = lane + t * 32;
        v[t] = (c < NROI) ? p[c] : -1e30f;
        mx = fmaxf(mx, v[t]);
    }
#pragma unroll
    for (int o = 16; o; o >>= 1) mx = fmaxf(mx, __shfl_xor_sync(0xffffffffu, mx, o));

    float s = 0.f;
#pragma unroll
    for (int t = 0; t < 13; t++) {
        v[t] = __expf(v[t] - mx);
        s += v[t];
    }
#pragma unroll
    for (int o = 16; o; o >>= 1) s += __shfl_xor_sync(0xffffffffu, s, o);
    float inv = 1.f / s;

#pragma unroll
    for (int t = 0; t < 13; t++) {
        int c = lane + t * 32;
        if (c < NROI) p[c] = v[t] * inv;
    }
}

// ---------------------------------------------------------------------------
extern "C" void kernel_launch(void* const* d_in, const int* in_sizes, int n_in,
                              void* d_out, int out_size) {
    const float* x    = (const float*)d_in[0];
    const int*   mask = (const int*)  d_in[1];
    const float* w    = (const float*)d_in[2];
    float* out = (float*)d_out;

    cudaFuncSetAttribute(gemm_qk_mma_kernel,
                         cudaFuncAttributeMaxDynamicSharedMemorySize, SMEM1_DYN);

    {
        int total = (M_TOT + DPAD) * (CDIM / 2);
        convert_kernel<<<(total + 255) / 256, 256>>>(x, w);
    }
    roi_mask_kernel<<<(M_TOT + 255) / 256, 256>>>(mask);

    dim3 gg(DPAD / BN1, M_TOT / BM1);   // (12, 100)
    gemm_qk_mma_kernel<<<gg, 256, SMEM1_DYN>>>();

    dim3 g3((NROI + BN - 1) / BN, (NROI + BM - 1) / BM, BH);  // (7,7,384)
    logits_kernel<<<g3, 256>>>(out);

    softmax_kernel<<<(BH * NROI + 7) / 8, 256>>>(out);
}

// round 5
// speedup vs baseline: 1.3979x; 1.0120x over previous
#include <cuda_runtime.h>
#include <cuda_bf16.h>
#include <math.h>
#include <stdint.h>

// ---------------------------------------------------------------------------
// Problem constants
// ---------------------------------------------------------------------------
#define BATCH 32
#define NROI  400
#define CDIM  720
#define HEADS 12
#define HD    60
#define M_TOT (BATCH*NROI)        // 12800
#define DTOT  1440                // q+k cols (v unused)
#define DPAD  1536                // grid padding (w has 2160 rows: safe to read)
#define BH    (BATCH*HEADS)       // 384

// GEMM1 tiling
#define BM1 128
#define BN1 128
#define BK1 48
#define NK_ITER (CDIM/BK1)        // 15
#define PITCH_B 112               // bytes per smem row (96 data + 16 pad)
#define TILE_BYTES (BM1*PITCH_B)  // 14336
#define STAGE_BYTES (4*TILE_BYTES)         // A_hi A_lo B_hi B_lo = 57344
#define SMEM1_DYN (2*STAGE_BYTES)          // 114688

// ---------------------------------------------------------------------------
// Device scratch (allocation-free rule)
// ---------------------------------------------------------------------------
__device__ __align__(256) float g_q[(size_t)BH*NROI*HD];
__device__ __align__(256) float g_k[(size_t)BH*NROI*HD];
__device__ int g_roim[M_TOT];
__device__ __align__(256) __nv_bfloat16 g_xhi[(size_t)M_TOT*CDIM];
__device__ __align__(256) __nv_bfloat16 g_xlo[(size_t)M_TOT*CDIM];
__device__ __align__(256) __nv_bfloat16 g_whi[(size_t)DPAD*CDIM];
__device__ __align__(256) __nv_bfloat16 g_wlo[(size_t)DPAD*CDIM];

// ---------------------------------------------------------------------------
// PTX helpers — compute_103-safe only (mma.sync / ldmatrix / cp.async)
// ---------------------------------------------------------------------------
__device__ __forceinline__ uint32_t smem_u32(const void* p) {
    uint32_t a;
    asm("{ .reg .u64 t; cvta.to.shared.u64 t, %1; cvt.u32.u64 %0, t; }" : "=r"(a) : "l"(p));
    return a;
}
__device__ __forceinline__ void cp_async16(uint32_t saddr, const void* gaddr) {
    asm volatile("cp.async.cg.shared.global [%0], [%1], 16;" :: "r"(saddr), "l"(gaddr));
}
#define CP_COMMIT() asm volatile("cp.async.commit_group;")
#define CP_WAIT(n)  asm volatile("cp.async.wait_group %0;" :: "n"(n))

__device__ __forceinline__ void ldm_x4(uint32_t* r, uint32_t addr) {
    asm volatile("ldmatrix.sync.aligned.m8n8.x4.shared.b16 {%0,%1,%2,%3}, [%4];"
                 : "=r"(r[0]), "=r"(r[1]), "=r"(r[2]), "=r"(r[3]) : "r"(addr));
}
__device__ __forceinline__ void ldm_x2(uint32_t* r, uint32_t addr) {
    asm volatile("ldmatrix.sync.aligned.m8n8.x2.shared.b16 {%0,%1}, [%2];"
                 : "=r"(r[0]), "=r"(r[1]) : "r"(addr));
}
__device__ __forceinline__ void mma_bf16(float* d, const uint32_t* a, const uint32_t* b) {
    asm volatile(
        "mma.sync.aligned.m16n8k16.row.col.f32.bf16.bf16.f32 "
        "{%0,%1,%2,%3}, {%4,%5,%6,%7}, {%8,%9}, {%0,%1,%2,%3};"
        : "+f"(d[0]), "+f"(d[1]), "+f"(d[2]), "+f"(d[3])
        : "r"(a[0]), "r"(a[1]), "r"(a[2]), "r"(a[3]), "r"(b[0]), "r"(b[1]));
}

// ---------------------------------------------------------------------------
// Kernel 0: fp32 -> bf16 hi/lo split (x rows, then w rows 0..DPAD-1)
// ---------------------------------------------------------------------------
__global__ void convert_kernel(const float* __restrict__ x, const float* __restrict__ w) {
    int idx = blockIdx.x * 256 + threadIdx.x;
    const int pairs = CDIM / 2;                     // 360
    const int total = (M_TOT + DPAD) * pairs;
    if (idx >= total) return;
    int row = idx / pairs;
    int c = (idx - row * pairs) * 2;
    const float* src;
    __nv_bfloat16 *hi, *lo;
    if (row < M_TOT) {
        src = x + (size_t)row * CDIM;
        hi = g_xhi + (size_t)row * CDIM; lo = g_xlo + (size_t)row * CDIM;
    } else {
        int r = row - M_TOT;
        src = w + (size_t)r * CDIM;
        hi = g_whi + (size_t)r * CDIM; lo = g_wlo + (size_t)r * CDIM;
    }
    float a0 = src[c], a1 = src[c + 1];
    __nv_bfloat16 h0 = __float2bfloat16(a0), h1 = __float2bfloat16(a1);
    hi[c] = h0; hi[c + 1] = h1;
    lo[c]     = __float2bfloat16(a0 - __bfloat162float(h0));
    lo[c + 1] = __float2bfloat16(a1 - __bfloat162float(h1));
}

// ---------------------------------------------------------------------------
// Kernel 1: roi_mask[b,n] = any(mask[b,:,n] != 0)
// ---------------------------------------------------------------------------
__global__ void roi_mask_kernel(const int* __restrict__ mask) {
    int idx = blockIdx.x * blockDim.x + threadIdx.x;
    if (idx >= M_TOT) return;
    int b = idx / NROI, n = idx % NROI;
    const int* p = mask + (size_t)b * CDIM * NROI + n;
    int s = 0;
    for (int c = 0; c < CDIM; c++) {
        s |= p[(size_t)c * NROI];
        if (s) break;
    }
    g_roim[idx] = (s != 0);
}

// ---------------------------------------------------------------------------
// Kernel 2: HMMA bf16-split GEMM.  D[m,d] = sum_c x[m,c]*w[d,c]
// grid (DPAD/128=12, M_TOT/128=100), 256 threads (8 warps, 2x4).
// ---------------------------------------------------------------------------
__device__ __forceinline__ void issue_stage_loads(uint32_t sbase,
                                                  int m0, int d0, int k0, int tid) {
    // 4 tiles x 768 16B-chunks, 6 chunks (96B) per 128 rows
    const __nv_bfloat16* gsrc[4] = {g_xhi, g_xlo, g_whi, g_wlo};
    const int row0[4] = {m0, m0, d0, d0};
#pragma unroll
    for (int t = 0; t < 4; t++) {
        uint32_t sb = sbase + t * TILE_BYTES;
        const __nv_bfloat16* g = gsrc[t];
#pragma unroll
        for (int it = 0; it < 3; it++) {
            int c = tid + it * 256;               // 0..767
            int r = c / 6, ch = c - r * 6;
            cp_async16(sb + r * PITCH_B + ch * 16,
                       g + (size_t)(row0[t] + r) * CDIM + k0 + ch * 8);
        }
    }
}

__global__ __launch_bounds__(256, 1) void gemm_qk_mma_kernel() {
    extern __shared__ __align__(128) char sm[];

    const int tid = threadIdx.x;
    const int wid = tid >> 5;
    const int lane = tid & 31;
    const int warp_m = wid >> 2;          // 0..1 : 64 rows each
    const int warp_n = wid & 3;           // 0..3 : 32 cols each
    const int m0 = blockIdx.y * BM1;
    const int d0 = blockIdx.x * BN1;

    const uint32_t sbase = smem_u32(sm);

    float acc[4][4][4];
#pragma unroll
    for (int i = 0; i < 4; i++)
#pragma unroll
        for (int j = 0; j < 4; j++)
#pragma unroll
            for (int e = 0; e < 4; e++) acc[i][j][e] = 0.f;

    issue_stage_loads(sbase, m0, d0, 0, tid);
    CP_COMMIT();

    // per-lane ldmatrix base offsets
    const int a_row = warp_m * 64 + (lane & 15);
    const int a_colb = (lane >> 4) * 16;                 // byte offset of k-half
    const int b_row = warp_n * 32 + (lane & 7);
    const int b_colb = ((lane >> 3) & 1) * 16;

    for (int kt = 0; kt < NK_ITER; kt++) {
        if (kt + 1 < NK_ITER) {
            issue_stage_loads(sbase + ((kt + 1) & 1) * STAGE_BYTES, m0, d0,
                              (kt + 1) * BK1, tid);
            CP_COMMIT();
            CP_WAIT(1);
        } else {
            CP_WAIT(0);
        }
        __syncthreads();

        uint32_t st = sbase + (kt & 1) * STAGE_BYTES;
        uint32_t a_hi_s = st;
        uint32_t a_lo_s = st + TILE_BYTES;
        uint32_t b_hi_s = st + 2 * TILE_BYTES;
        uint32_t b_lo_s = st + 3 * TILE_BYTES;

#pragma unroll
        for (int ks = 0; ks < BK1 / 16; ks++) {          // 3 k16 steps
            uint32_t ahi[4][4], alo[4][4];
#pragma unroll
            for (int mf = 0; mf < 4; mf++) {
                uint32_t off = (uint32_t)(a_row + mf * 16) * PITCH_B + ks * 32 + a_colb;
                ldm_x4(ahi[mf], a_hi_s + off);
                ldm_x4(alo[mf], a_lo_s + off);
            }
            uint32_t bhi[4][2], blo[4][2];
#pragma unroll
            for (int nf = 0; nf < 4; nf++) {
                uint32_t off = (uint32_t)(b_row + nf * 8) * PITCH_B + ks * 32 + b_colb;
                ldm_x2(bhi[nf], b_hi_s + off);
                ldm_x2(blo[nf], b_lo_s + off);
            }
#pragma unroll
            for (int mf = 0; mf < 4; mf++)
#pragma unroll
                for (int nf = 0; nf < 4; nf++) {
                    mma_bf16(acc[mf][nf], ahi[mf], bhi[nf]);
                    mma_bf16(acc[mf][nf], ahi[mf], blo[nf]);
                    mma_bf16(acc[mf][nf], alo[mf], bhi[nf]);
                }
        }
        __syncthreads();
    }

    // Epilogue: regs -> smem (fp32, pitch 132) -> coalesced scatter
    float* stage = (float*)sm;            // 128 x 132 floats = 67.6KB <= SMEM1_DYN
#pragma unroll
    for (int mf = 0; mf < 4; mf++)
#pragma unroll
        for (int nf = 0; nf < 4; nf++) {
            int r0 = warp_m * 64 + mf * 16 + (lane >> 2);
            int c0 = warp_n * 32 + nf * 8 + (lane & 3) * 2;
            stage[r0 * 132 + c0]           = acc[mf][nf][0];
            stage[r0 * 132 + c0 + 1]       = acc[mf][nf][1];
            stage[(r0 + 8) * 132 + c0]     = acc[mf][nf][2];
            stage[(r0 + 8) * 132 + c0 + 1] = acc[mf][nf][3];
        }
    __syncthreads();

    // FIXED: q/k routing decided PER COLUMN (720 is not 128-aligned).
    for (int i = tid; i < BM1 * BN1; i += 256) {
        int r = i >> 7, col = i & 127;
        int d = d0 + col;
        if (d >= DTOT) continue;
        int m = m0 + r;
        int b = m / NROI, n = m - b * NROI;
        float v = stage[r * 132 + col];
        if (d < CDIM) {
            int h = d / HD, e = d - h * HD;
            g_q[(((size_t)b * HEADS + h) * NROI + n) * HD + e] = v;
        } else {
            int dd = d - CDIM;
            int h = dd / HD, e = dd - h * HD;
            g_k[(((size_t)b * HEADS + h) * NROI + n) * HD + e] = v;
        }
    }
}

// ---------------------------------------------------------------------------
// Kernel 3: batched logits GEMM + scale + roi mask (fp32)
// ---------------------------------------------------------------------------
#define BM 64
#define BN 64
__global__ __launch_bounds__(256) void logits_kernel(float* __restrict__ out) {
    __shared__ float Qs[HD][BM + 4];
    __shared__ float Ks[HD][BN + 4];

    const int bh = blockIdx.z;
    const int b  = bh / HEADS;
    const int n0 = blockIdx.y * BM;
    const int c0 = blockIdx.x * BN;
    const int tid = threadIdx.x;
    const int tx = tid & 15;
    const int ty = tid >> 4;

    const size_t bh_off = (size_t)bh * NROI * HD;
    const float scale = rsqrtf((float)HD);

    for (int i = tid; i < BM * HD; i += 256) {
        int r = i / HD, c = i % HD;
        int qrow = n0 + r;
        Qs[c][r] = (qrow < NROI) ? g_q[bh_off + (size_t)qrow * HD + c] : 0.f;
        int krow = c0 + r;
        Ks[c][r] = (krow < NROI) ? g_k[bh_off + (size_t)krow * HD + c] : 0.f;
    }
    __syncthreads();

    float acc[4][4];
#pragma unroll
    for (int i = 0; i < 4; i++)
#pragma unroll
        for (int j = 0; j < 4; j++) acc[i][j] = 0.f;

#pragma unroll 4
    for (int kk = 0; kk < HD; kk++) {
        float a[4], bb_[4];
#pragma unroll
        for (int i = 0; i < 4; i++) a[i] = Qs[kk][ty * 4 + i];
#pragma unroll
        for (int j = 0; j < 4; j++) bb_[j] = Ks[kk][tx * 4 + j];
#pragma unroll
        for (int i = 0; i < 4; i++)
#pragma unroll
            for (int j = 0; j < 4; j++) acc[i][j] += a[i] * bb_[j];
    }

#pragma unroll
    for (int i = 0; i < 4; i++) {
        int n = n0 + ty * 4 + i;
        if (n >= NROI) continue;
        float* row = out + ((size_t)bh * NROI + n) * NROI;
#pragma unroll
        for (int j = 0; j < 4; j++) {
            int m = c0 + tx * 4 + j;
            if (m >= NROI) continue;
            float v = acc[i][j] * scale;
            if (!g_roim[b * NROI + m]) v = -10000.0f;
            row[m] = v;
        }
    }
}

// ---------------------------------------------------------------------------
// Kernel 4: in-place row softmax. One warp per row of 400.
// ---------------------------------------------------------------------------
__global__ __launch_bounds__(256) void softmax_kernel(float* __restrict__ out) {
    const int row = blockIdx.x * 8 + (threadIdx.x >> 5);
    if (row >= BH * NROI) return;
    const int lane = threadIdx.x & 31;
    float* p = out + (size_t)row * NROI;

    float v[13];
    float mx = -1e30f;
#pragma unroll
    for (int t = 0; t < 13; t++) {
        int c = lane + t * 32;
        v[t] = (c < NROI) ? p[c] : -1e30f;
        mx = fmaxf(mx, v[t]);
    }
#pragma unroll
    for (int o = 16; o; o >>= 1) mx = fmaxf(mx, __shfl_xor_sync(0xffffffffu, mx, o));

    float s = 0.f;
#pragma unroll
    for (int t = 0; t < 13; t++) {
        v[t] = __expf(v[t] - mx);
        s += v[t];
    }
#pragma unroll
    for (int o = 16; o; o >>= 1) s += __shfl_xor_sync(0xffffffffu, s, o);
    float inv = 1.f / s;

#pragma unroll
    for (int t = 0; t < 13; t++) {
        int c = lane + t * 32;
        if (c < NROI) p[c] = v[t] * inv;
    }
}

// ---------------------------------------------------------------------------
extern "C" void kernel_launch(void* const* d_in, const int* in_sizes, int n_in,
                              void* d_out, int out_size) {
    const float* x    = (const float*)d_in[0];
    const int*   mask = (const int*)  d_in[1];
    const float* w    = (const float*)d_in[2];
    float* out = (float*)d_out;

    cudaFuncSetAttribute(gemm_qk_mma_kernel,
                         cudaFuncAttributeMaxDynamicSharedMemorySize, SMEM1_DYN);

    {
        int total = (M_TOT + DPAD) * (CDIM / 2);
        convert_kernel<<<(total + 255) / 256, 256>>>(x, w);
    }
    roi_mask_kernel<<<(M_TOT + 255) / 256, 256>>>(mask);

    dim3 gg(DPAD / BN1, M_TOT / BM1);   // (12, 100)
    gemm_qk_mma_kernel<<<gg, 256, SMEM1_DYN>>>();

    dim3 g3((NROI + BN - 1) / BN, (NROI + BM - 1) / BM, BH);  // (7,7,384)
    logits_kernel<<<g3, 256>>>(out);

    softmax_kernel<<<(BH * NROI + 7) / 8, 256>>>(out);
}

// round 6
// speedup vs baseline: 2.7599x; 1.9743x over previous
#include <cuda_runtime.h>
#include <cuda_bf16.h>
#include <math.h>
#include <stdint.h>

// ---------------------------------------------------------------------------
// Problem constants
// ---------------------------------------------------------------------------
#define BATCH 32
#define NROI  400
#define CDIM  720
#define HEADS 12
#define HD    60
#define HDP   64                  // head dim padded (pad cols stay zero forever)
#define M_TOT (BATCH*NROI)        // 12800
#define DTOT  1440                // q+k cols (v unused)
#define DPAD  1536
#define BH    (BATCH*HEADS)       // 384

// GEMM1 tiling
#define BM1 128
#define BN1 128
#define BK1 48
#define NK_ITER (CDIM/BK1)        // 15
#define PITCH_B 112
#define TILE_BYTES (BM1*PITCH_B)  // 14336
#define STAGE_BYTES (4*TILE_BYTES)
#define SMEM1_DYN (2*STAGE_BYTES) // 114688

// Fused attention tiling
#define NKP   448                 // keys padded: 8 warps x 56 cols
#define NFRAG 7                   // 56/8
#define PITCH 144                 // smem row pitch bytes (128 data + 16 pad)
#define SQHI  0
#define SQLO  9216                // 64*144
#define SKHI  18432
#define SKLO  82944               // 18432 + 448*144
#define SRED  147456              // 64*8 floats
#define SRST  149504              // 64 floats
#define SROI  149760              // 448 ints (only 400 used)
#define SMEM_ATT 151808

// ---------------------------------------------------------------------------
// Device scratch (zero-initialized once; pad regions never written -> stay 0)
// ---------------------------------------------------------------------------
__device__ int g_roim[M_TOT];
__device__ __align__(256) __nv_bfloat16 g_xhi[(size_t)M_TOT*CDIM];
__device__ __align__(256) __nv_bfloat16 g_xlo[(size_t)M_TOT*CDIM];
__device__ __align__(256) __nv_bfloat16 g_whi[(size_t)DPAD*CDIM];
__device__ __align__(256) __nv_bfloat16 g_wlo[(size_t)DPAD*CDIM];
__device__ __align__(256) __nv_bfloat16 g_qhi[(size_t)BH*NROI*HDP];
__device__ __align__(256) __nv_bfloat16 g_qlo[(size_t)BH*NROI*HDP];
__device__ __align__(256) __nv_bfloat16 g_khi[(size_t)BH*NROI*HDP];
__device__ __align__(256) __nv_bfloat16 g_klo[(size_t)BH*NROI*HDP];

// ---------------------------------------------------------------------------
// PTX helpers (compute_103-safe: mma.sync / ldmatrix / cp.async only)
// ---------------------------------------------------------------------------
__device__ __forceinline__ uint32_t smem_u32(const void* p) {
    uint32_t a;
    asm("{ .reg .u64 t; cvta.to.shared.u64 t, %1; cvt.u32.u64 %0, t; }" : "=r"(a) : "l"(p));
    return a;
}
__device__ __forceinline__ void cp_async16(uint32_t saddr, const void* gaddr) {
    asm volatile("cp.async.cg.shared.global [%0], [%1], 16;" :: "r"(saddr), "l"(gaddr));
}
#define CP_COMMIT() asm volatile("cp.async.commit_group;")
#define CP_WAIT(n)  asm volatile("cp.async.wait_group %0;" :: "n"(n))

__device__ __forceinline__ void ldm_x4(uint32_t* r, uint32_t addr) {
    asm volatile("ldmatrix.sync.aligned.m8n8.x4.shared.b16 {%0,%1,%2,%3}, [%4];"
                 : "=r"(r[0]), "=r"(r[1]), "=r"(r[2]), "=r"(r[3]) : "r"(addr));
}
__device__ __forceinline__ void ldm_x2(uint32_t* r, uint32_t addr) {
    asm volatile("ldmatrix.sync.aligned.m8n8.x2.shared.b16 {%0,%1}, [%2];"
                 : "=r"(r[0]), "=r"(r[1]) : "r"(addr));
}
__device__ __forceinline__ void mma_bf16(float* d, const uint32_t* a, const uint32_t* b) {
    asm volatile(
        "mma.sync.aligned.m16n8k16.row.col.f32.bf16.bf16.f32 "
        "{%0,%1,%2,%3}, {%4,%5,%6,%7}, {%8,%9}, {%0,%1,%2,%3};"
        : "+f"(d[0]), "+f"(d[1]), "+f"(d[2]), "+f"(d[3])
        : "r"(a[0]), "r"(a[1]), "r"(a[2]), "r"(a[3]), "r"(b[0]), "r"(b[1]));
}

// ---------------------------------------------------------------------------
// Kernel 0: fp32 -> bf16 hi/lo split (x rows, then w rows 0..DPAD-1)
// ---------------------------------------------------------------------------
__global__ void convert_kernel(const float* __restrict__ x, const float* __restrict__ w) {
    int idx = blockIdx.x * 256 + threadIdx.x;
    const int pairs = CDIM / 2;
    const int total = (M_TOT + DPAD) * pairs;
    if (idx >= total) return;
    int row = idx / pairs;
    int c = (idx - row * pairs) * 2;
    const float* src;
    __nv_bfloat16 *hi, *lo;
    if (row < M_TOT) {
        src = x + (size_t)row * CDIM;
        hi = g_xhi + (size_t)row * CDIM; lo = g_xlo + (size_t)row * CDIM;
    } else {
        int r = row - M_TOT;
        src = w + (size_t)r * CDIM;
        hi = g_whi + (size_t)r * CDIM; lo = g_wlo + (size_t)r * CDIM;
    }
    float a0 = src[c], a1 = src[c + 1];
    __nv_bfloat16 h0 = __float2bfloat16(a0), h1 = __float2bfloat16(a1);
    hi[c] = h0; hi[c + 1] = h1;
    lo[c]     = __float2bfloat16(a0 - __bfloat162float(h0));
    lo[c + 1] = __float2bfloat16(a1 - __bfloat162float(h1));
}

// ---------------------------------------------------------------------------
// Kernel 1: roi_mask — full coalesced scan, no serial dependence.
// grid (32, 2), 256 threads (200 active): thread owns one (b, n) column.
// ---------------------------------------------------------------------------
__global__ void roi_mask_kernel(const int* __restrict__ mask) {
    int n = blockIdx.y * 200 + threadIdx.x;
    if (threadIdx.x >= 200 || n >= NROI) return;
    int b = blockIdx.x;
    const int* p = mask + (size_t)b * CDIM * NROI + n;
    int s = 0;
#pragma unroll 8
    for (int c = 0; c < CDIM; c++) s |= p[(size_t)c * NROI];
    g_roim[b * NROI + n] = (s != 0);
}

// ---------------------------------------------------------------------------
// Kernel 2: HMMA bf16-split GEMM (unchanged mainloop).
// Epilogue writes q/k as bf16 hi/lo into (bh, n, HDP=64) padded layout.
// ---------------------------------------------------------------------------
__device__ __forceinline__ void issue_stage_loads(uint32_t sbase,
                                                  int m0, int d0, int k0, int tid) {
    const __nv_bfloat16* gsrc[4] = {g_xhi, g_xlo, g_whi, g_wlo};
    const int row0[4] = {m0, m0, d0, d0};
#pragma unroll
    for (int t = 0; t < 4; t++) {
        uint32_t sb = sbase + t * TILE_BYTES;
        const __nv_bfloat16* g = gsrc[t];
#pragma unroll
        for (int it = 0; it < 3; it++) {
            int c = tid + it * 256;
            int r = c / 6, ch = c - r * 6;
            cp_async16(sb + r * PITCH_B + ch * 16,
                       g + (size_t)(row0[t] + r) * CDIM + k0 + ch * 8);
        }
    }
}

__global__ __launch_bounds__(256, 1) void gemm_qk_mma_kernel() {
    extern __shared__ __align__(128) char sm[];

    const int tid = threadIdx.x;
    const int wid = tid >> 5;
    const int lane = tid & 31;
    const int warp_m = wid >> 2;
    const int warp_n = wid & 3;
    const int m0 = blockIdx.y * BM1;
    const int d0 = blockIdx.x * BN1;

    const uint32_t sbase = smem_u32(sm);

    float acc[4][4][4];
#pragma unroll
    for (int i = 0; i < 4; i++)
#pragma unroll
        for (int j = 0; j < 4; j++)
#pragma unroll
            for (int e = 0; e < 4; e++) acc[i][j][e] = 0.f;

    issue_stage_loads(sbase, m0, d0, 0, tid);
    CP_COMMIT();

    const int a_row = warp_m * 64 + (lane & 15);
    const int a_colb = (lane >> 4) * 16;
    const int b_row = warp_n * 32 + (lane & 7);
    const int b_colb = ((lane >> 3) & 1) * 16;

    for (int kt = 0; kt < NK_ITER; kt++) {
        if (kt + 1 < NK_ITER) {
            issue_stage_loads(sbase + ((kt + 1) & 1) * STAGE_BYTES, m0, d0,
                              (kt + 1) * BK1, tid);
            CP_COMMIT();
            CP_WAIT(1);
        } else {
            CP_WAIT(0);
        }
        __syncthreads();

        uint32_t st = sbase + (kt & 1) * STAGE_BYTES;
        uint32_t a_hi_s = st;
        uint32_t a_lo_s = st + TILE_BYTES;
        uint32_t b_hi_s = st + 2 * TILE_BYTES;
        uint32_t b_lo_s = st + 3 * TILE_BYTES;

#pragma unroll
        for (int ks = 0; ks < BK1 / 16; ks++) {
            uint32_t ahi[4][4], alo[4][4];
#pragma unroll
            for (int mf = 0; mf < 4; mf++) {
                uint32_t off = (uint32_t)(a_row + mf * 16) * PITCH_B + ks * 32 + a_colb;
                ldm_x4(ahi[mf], a_hi_s + off);
                ldm_x4(alo[mf], a_lo_s + off);
            }
            uint32_t bhi[4][2], blo[4][2];
#pragma unroll
            for (int nf = 0; nf < 4; nf++) {
                uint32_t off = (uint32_t)(b_row + nf * 8) * PITCH_B + ks * 32 + b_colb;
                ldm_x2(bhi[nf], b_hi_s + off);
                ldm_x2(blo[nf], b_lo_s + off);
            }
#pragma unroll
            for (int mf = 0; mf < 4; mf++)
#pragma unroll
                for (int nf = 0; nf < 4; nf++) {
                    mma_bf16(acc[mf][nf], ahi[mf], bhi[nf]);
                    mma_bf16(acc[mf][nf], ahi[mf], blo[nf]);
                    mma_bf16(acc[mf][nf], alo[mf], bhi[nf]);
                }
        }
        __syncthreads();
    }

    // regs -> smem (fp32) -> bf16 hi/lo scatter (per-column q/k routing)
    float* stage = (float*)sm;
#pragma unroll
    for (int mf = 0; mf < 4; mf++)
#pragma unroll
        for (int nf = 0; nf < 4; nf++) {
            int r0 = warp_m * 64 + mf * 16 + (lane >> 2);
            int c0 = warp_n * 32 + nf * 8 + (lane & 3) * 2;
            stage[r0 * 132 + c0]           = acc[mf][nf][0];
            stage[r0 * 132 + c0 + 1]       = acc[mf][nf][1];
            stage[(r0 + 8) * 132 + c0]     = acc[mf][nf][2];
            stage[(r0 + 8) * 132 + c0 + 1] = acc[mf][nf][3];
        }
    __syncthreads();

    for (int i = tid; i < BM1 * BN1; i += 256) {
        int r = i >> 7, col = i & 127;
        int d = d0 + col;
        if (d >= DTOT) continue;
        int m = m0 + r;
        int b = m / NROI, n = m - b * NROI;
        float v = stage[r * 132 + col];
        __nv_bfloat16 h = __float2bfloat16(v);
        __nv_bfloat16 l = __float2bfloat16(v - __bfloat162float(h));
        __nv_bfloat16 *ph, *pl;
        int hh, e;
        if (d < CDIM) { hh = d / HD; e = d - hh * HD; ph = g_qhi; pl = g_qlo; }
        else { int dd = d - CDIM; hh = dd / HD; e = dd - hh * HD; ph = g_khi; pl = g_klo; }
        size_t idx = (((size_t)b * HEADS + hh) * NROI + n) * HDP + e;
        ph[idx] = h;
        pl[idx] = l;
    }
}

// ---------------------------------------------------------------------------
// Kernel 3: FUSED logits + mask + softmax.
// grid (7, 384): x = 64-row query block, y = bh. 256 threads (8 warps).
// Warp w computes 64 rows x cols [w*56, w*56+56) with split-bf16 HMMA,
// then CTA-wide row softmax, single write of probabilities.
// ---------------------------------------------------------------------------
__global__ __launch_bounds__(256, 1) void attn_fused_kernel(float* __restrict__ out) {
    extern __shared__ __align__(128) char sm[];
    const uint32_t sbase = smem_u32(sm);

    const int tid = threadIdx.x;
    const int wid = tid >> 5;
    const int lane = tid & 31;
    const int r0 = blockIdx.x * 64;
    const int bh = blockIdx.y;
    const int b = bh / HEADS;

    float* red  = (float*)(sm + SRED);    // [64][8] partials
    float* rst  = (float*)(sm + SRST);    // [64] rowmax then 1/sum
    int*   sroi = (int*)(sm + SROI);

    // ---- loads ----
    // Q tile (64 x 64 bf16 hi/lo), zero rows beyond NROI
    for (int i = tid; i < 512; i += 256) {
        int row = i >> 3, ch = i & 7;
        int qrow = r0 + row;
        uint32_t dh = sbase + SQHI + row * PITCH + ch * 16;
        uint32_t dl = sbase + SQLO + row * PITCH + ch * 16;
        if (qrow < NROI) {
            size_t g = ((size_t)bh * NROI + qrow) * HDP + ch * 8;
            cp_async16(dh, g_qhi + g);
            cp_async16(dl, g_qlo + g);
        } else {
            uint4 z = {0, 0, 0, 0};
            *(uint4*)(sm + SQHI + row * PITCH + ch * 16) = z;
            *(uint4*)(sm + SQLO + row * PITCH + ch * 16) = z;
        }
    }
    // K tile: all 400 keys (hi/lo)
    for (int i = tid; i < 3200; i += 256) {
        int row = i >> 3, ch = i & 7;
        size_t g = ((size_t)bh * NROI + row) * HDP + ch * 8;
        cp_async16(sbase + SKHI + row * PITCH + ch * 16, g_khi + g);
        cp_async16(sbase + SKLO + row * PITCH + ch * 16, g_klo + g);
    }
    // zero K pad rows 400..447
    for (int i = tid; i < 384; i += 256) {
        int row = NROI + (i >> 3), ch = i & 7;
        uint4 z = {0, 0, 0, 0};
        *(uint4*)(sm + SKHI + row * PITCH + ch * 16) = z;
        *(uint4*)(sm + SKLO + row * PITCH + ch * 16) = z;
    }
    // roi flags
    for (int i = tid; i < NROI; i += 256) sroi[i] = g_roim[b * NROI + i];
    CP_COMMIT();
    CP_WAIT(0);
    __syncthreads();

    // ---- MMA: 64 x 56 per warp, K=64 (4 k16 steps), 3-product split ----
    float acc[4][NFRAG][4];
#pragma unroll
    for (int i = 0; i < 4; i++)
#pragma unroll
        for (int j = 0; j < NFRAG; j++)
#pragma unroll
            for (int e = 0; e < 4; e++) acc[i][j][e] = 0.f;

    const int a_row = lane & 15;
    const int a_colb = (lane >> 4) * 16;
    const int b_lane_row = lane & 7;
    const int b_colb = ((lane >> 3) & 1) * 16;

#pragma unroll
    for (int ks = 0; ks < 4; ks++) {
        uint32_t ahi[4][4], alo[4][4];
#pragma unroll
        for (int mf = 0; mf < 4; mf++) {
            uint32_t off = (uint32_t)(a_row + mf * 16) * PITCH + ks * 32 + a_colb;
            ldm_x4(ahi[mf], sbase + SQHI + off);
            ldm_x4(alo[mf], sbase + SQLO + off);
        }
#pragma unroll
        for (int nf = 0; nf < NFRAG; nf++) {
            int krow = wid * 56 + nf * 8 + b_lane_row;
            uint32_t off = (uint32_t)krow * PITCH + ks * 32 + b_colb;
            uint32_t bhi[2], blo[2];
            ldm_x2(bhi, sbase + SKHI + off);
            ldm_x2(blo, sbase + SKLO + off);
#pragma unroll
            for (int mf = 0; mf < 4; mf++) {
                mma_bf16(acc[mf][nf], ahi[mf], bhi);
                mma_bf16(acc[mf][nf], ahi[mf], blo);
                mma_bf16(acc[mf][nf], alo[mf], bhi);
            }
        }
    }

    // ---- scale + mask (in regs) ----
    const float scale = rsqrtf((float)HD);
    const int lrow = lane >> 2;
    const int lcol2 = (lane & 3) * 2;
    const float NEG_INF = -__int_as_float(0x7f800000);   // -inf

#pragma unroll
    for (int nf = 0; nf < NFRAG; nf++) {
        int c0 = wid * 56 + nf * 8 + lcol2;
        int c1 = c0 + 1;
        bool pv0 = (c0 < NROI), pv1 = (c1 < NROI);
        float m0 = !pv0 ? NEG_INF : (sroi[c0] ? 0.f : 1.f);
        float m1 = !pv1 ? NEG_INF : (sroi[c1] ? 0.f : 1.f);
#pragma unroll
        for (int mf = 0; mf < 4; mf++) {
            // m==0: keep scaled; m==1: -10000; m==-inf: -inf
            acc[mf][nf][0] = (m0 == 0.f) ? acc[mf][nf][0] * scale : (pv0 ? -10000.f : NEG_INF);
            acc[mf][nf][1] = (m1 == 0.f) ? acc[mf][nf][1] * scale : (pv1 ? -10000.f : NEG_INF);
            acc[mf][nf][2] = (m0 == 0.f) ? acc[mf][nf][2] * scale : (pv0 ? -10000.f : NEG_INF);
            acc[mf][nf][3] = (m1 == 0.f) ? acc[mf][nf][3] * scale : (pv1 ? -10000.f : NEG_INF);
        }
    }

    // ---- row max: thread -> quad -> cross-warp ----
#pragma unroll
    for (int mf = 0; mf < 4; mf++) {
        float mlo = NEG_INF, mhi = NEG_INF;
#pragma unroll
        for (int nf = 0; nf < NFRAG; nf++) {
            mlo = fmaxf(mlo, fmaxf(acc[mf][nf][0], acc[mf][nf][1]));
            mhi = fmaxf(mhi, fmaxf(acc[mf][nf][2], acc[mf][nf][3]));
        }
        mlo = fmaxf(mlo, __shfl_xor_sync(0xffffffffu, mlo, 1));
        mlo = fmaxf(mlo, __shfl_xor_sync(0xffffffffu, mlo, 2));
        mhi = fmaxf(mhi, __shfl_xor_sync(0xffffffffu, mhi, 1));
        mhi = fmaxf(mhi, __shfl_xor_sync(0xffffffffu, mhi, 2));
        if ((lane & 3) == 0) {
            red[(mf * 16 + lrow) * 8 + wid] = mlo;
            red[(mf * 16 + lrow + 8) * 8 + wid] = mhi;
        }
    }
    __syncthreads();
    if (tid < 64) {
        float m = NEG_INF;
#pragma unroll
        for (int w = 0; w < 8; w++) m = fmaxf(m, red[tid * 8 + w]);
        rst[tid] = m;
    }
    __syncthreads();

    // ---- exp + row sum ----
#pragma unroll
    for (int mf = 0; mf < 4; mf++) {
        float slo = 0.f, shi = 0.f;
        float rmlo = rst[mf * 16 + lrow];
        float rmhi = rst[mf * 16 + lrow + 8];
#pragma unroll
        for (int nf = 0; nf < NFRAG; nf++) {
            float e0 = __expf(acc[mf][nf][0] - rmlo);
            float e1 = __expf(acc[mf][nf][1] - rmlo);
            float e2 = __expf(acc[mf][nf][2] - rmhi);
            float e3 = __expf(acc[mf][nf][3] - rmhi);
            acc[mf][nf][0] = e0; acc[mf][nf][1] = e1;
            acc[mf][nf][2] = e2; acc[mf][nf][3] = e3;
            slo += e0 + e1;
            shi += e2 + e3;
        }
        slo += __shfl_xor_sync(0xffffffffu, slo, 1);
        slo += __shfl_xor_sync(0xffffffffu, slo, 2);
        shi += __shfl_xor_sync(0xffffffffu, shi, 1);
        shi += __shfl_xor_sync(0xffffffffu, shi, 2);
        if ((lane & 3) == 0) {
            red[(mf * 16 + lrow) * 8 + wid] = slo;
            red[(mf * 16 + lrow + 8) * 8 + wid] = shi;
        }
    }
    __syncthreads();
    if (tid < 64) {
        float s = 0.f;
#pragma unroll
        for (int w = 0; w < 8; w++) s += red[tid * 8 + w];
        rst[tid] = 1.f / s;
    }
    __syncthreads();

    // ---- write probabilities (float2 per pair) ----
#pragma unroll
    for (int mf = 0; mf < 4; mf++) {
        int rlo_l = mf * 16 + lrow;
        int rhi_l = rlo_l + 8;
        int rlo = r0 + rlo_l, rhi = r0 + rhi_l;
        float ilo = rst[rlo_l], ihi = rst[rhi_l];
#pragma unroll
        for (int nf = 0; nf < NFRAG; nf++) {
            int c0 = wid * 56 + nf * 8 + lcol2;
            if (c0 >= NROI) continue;
            if (rlo < NROI) {
                float2 v = {acc[mf][nf][0] * ilo, acc[mf][nf][1] * ilo};
                *(float2*)(out + ((size_t)bh * NROI + rlo) * NROI + c0) = v;
            }
            if (rhi < NROI) {
                float2 v = {acc[mf][nf][2] * ihi, acc[mf][nf][3] * ihi};
                *(float2*)(out + ((size_t)bh * NROI + rhi) * NROI + c0) = v;
            }
        }
    }
}

// ---------------------------------------------------------------------------
extern "C" void kernel_launch(void* const* d_in, const int* in_sizes, int n_in,
                              void* d_out, int out_size) {
    const float* x    = (const float*)d_in[0];
    const int*   mask = (const int*)  d_in[1];
    const float* w    = (const float*)d_in[2];
    float* out = (float*)d_out;

    cudaFuncSetAttribute(gemm_qk_mma_kernel,
                         cudaFuncAttributeMaxDynamicSharedMemorySize, SMEM1_DYN);
    cudaFuncSetAttribute(attn_fused_kernel,
                         cudaFuncAttributeMaxDynamicSharedMemorySize, SMEM_ATT);

    {
        int total = (M_TOT + DPAD) * (CDIM / 2);
        convert_kernel<<<(total + 255) / 256, 256>>>(x, w);
    }
    roi_mask_kernel<<<dim3(BATCH, 2), 256>>>(mask);

    dim3 gg(DPAD / BN1, M_TOT / BM1);   // (12, 100)
    gemm_qk_mma_kernel<<<gg, 256, SMEM1_DYN>>>();

    dim3 ga(7, BH);                     // (row-blocks, bh)
    attn_fused_kernel<<<ga, 256, SMEM_ATT>>>(out);
}